// round 9
// baseline (speedup 1.0000x reference)
#include <cuda_runtime.h>
#include <cuda_fp16.h>
#include <cstdint>
#include <cfloat>

// VQ R9: fp16 hi-pass tensor screen + certified exact fp32 rescore.
// approx[m][k] = fp16(x).fp16(e) - 0.5||e||^2 stored fp16 in SMEM; any code
// within a rigorous error margin of the max is rescored exactly (fp32).

#define D    64
#define K    512
#define MT   128     // pixels per CTA
#define T    512     // threads per CTA (16 warps)

// SMEM layout (bytes)
#define SX_OFF    0                       // x tile fp32 [d][m]=[64][128]  32KB
#define BA_OFF    32768                   // codebook hi fp16 [512][128B]  64KB
#define SC_OFF    98304                   // scores fp16 [128][512]       128KB
#define SHES_OFF  229376                  // 512 f32
#define SBEST_OFF 231424                  // 128 int
#define SMEM_SZ   231936

__device__ __half g_ea[K * D];   // fp16 hi split, permuted+swizzled rows
__device__ float  g_hes[K];      // 0.5*||e||^2
__device__ int    g_mhbits = 0;  // max hes as int bits (hes>0, monotone)

// ---------------- helpers ----------------
__device__ __forceinline__ uint32_t smem_u32(const void* p) {
    uint32_t a;
    asm("{ .reg .u64 t; cvta.to.shared.u64 t, %1; cvt.u32.u64 %0, t; }" : "=r"(a) : "l"(p));
    return a;
}
#define MMA_F16(c, a0, a1, a2, a3, b0, b1)                                       \
    asm volatile("mma.sync.aligned.m16n8k16.row.col.f32.f16.f16.f32 "            \
        "{%0,%1,%2,%3},{%4,%5,%6,%7},{%8,%9},{%0,%1,%2,%3};"                     \
        : "+f"((c)[0]), "+f"((c)[1]), "+f"((c)[2]), "+f"((c)[3])                  \
        : "r"(a0), "r"(a1), "r"(a2), "r"(a3), "r"(b0), "r"(b1))

__device__ __forceinline__ void cp16(uint32_t dst, const void* src) {
    asm volatile("cp.async.cg.shared.global [%0], [%1], 16;" :: "r"(dst), "l"(src) : "memory");
}
#define CP_COMMIT() asm volatile("cp.async.commit_group;" ::: "memory")
#define CP_WAIT(n)  asm volatile("cp.async.wait_group %0;" :: "n"(n) : "memory")

__device__ __forceinline__ uint32_t pack2(__half x, __half y) {
    __half2 h = __halves2half2(x, y);
    return *(uint32_t*)&h;
}

// ---------------- prep: hi split codebook (permuted+swizzled), half norms ----
// element d = 32g+16c+8h+2rr+par -> slot ((g<<2)+rr+((k&1)<<2))&7, idx (2c+h)*2+par
__global__ void vq_prep(const float* __restrict__ embed) {
    int k = blockIdx.x, d = threadIdx.x;
    float v = embed[k * D + d];
    __half a = __float2half_rn(v);
    int g = d >> 5, kk = d & 31;
    int rr = (kk >> 1) & 3, h = (kk >> 3) & 1, c = (kk >> 4) & 1, par = kk & 1;
    int slot = ((g << 2) + rr + ((k & 1) << 2)) & 7;
    g_ea[k * 64 + slot * 8 + ((c << 1) + h) * 2 + par] = a;
    float s = v * v;
    #pragma unroll
    for (int o = 16; o > 0; o >>= 1) s += __shfl_down_sync(0xffffffffu, s, o);
    __shared__ float ws[2];
    if ((d & 31) == 0) ws[d >> 5] = s;
    __syncthreads();
    if (d == 0) {
        float hes = 0.5f * (ws[0] + ws[1]);
        g_hes[k] = hes;
        atomicMax(&g_mhbits, __float_as_int(hes));
    }
}

// ---------------- main ----------------
__global__ void __launch_bounds__(T, 1) vq_main(const float* __restrict__ x,
                                                const float* __restrict__ embed,
                                                float* __restrict__ outq,
                                                float* __restrict__ outi) {
    extern __shared__ __align__(1024) char smem[];
    uint32_t sb = smem_u32(smem);
    const int tid = threadIdx.x, wid = tid >> 5, lane = tid & 31;
    const int q = lane >> 2, r = lane & 3;
    const int wm = wid & 7;                  // m-group (16 pixels)
    const int wg = wid >> 3;                 // n-half (tiles 0..31 / 32..63)
    const int n0 = blockIdx.x * MT;
    const int b = n0 >> 12, hw0 = n0 & 4095;

    float* sx = (float*)(smem + SX_OFF);     // [d][128]
    float* shes = (float*)(smem + SHES_OFF);
    int* sbest = (int*)(smem + SBEST_OFF);

    // stage hi codebook (64KB) via cp.async
    #pragma unroll
    for (int t = 0; t < 8; t++) {
        int c = tid + t * T;                 // 4096 16B chunks
        cp16(sb + BA_OFF + c * 16, (const char*)g_ea + c * 16);
    }
    CP_COMMIT();

    // stage x tile: sx[c][j] = x[b][c][hw0+j]
    #pragma unroll
    for (int t = 0; t < 4; t++) {
        int i = tid + t * T;
        int c = i >> 5, j4 = (i & 31) << 2;
        float4 v = *(const float4*)(x + (((size_t)(b * D + c)) << 12) + hw0 + j4);
        *(float4*)(sx + c * MT + j4) = v;
    }
    shes[tid] = g_hes[tid];
    CP_WAIT(0);
    __syncthreads();

    // A hi fragments: rows m0+q, m0+q+8; Aa[cc][reg], k-lo = 16cc+2r (+8 for hi regs)
    const int m0 = wm * 16;
    uint32_t Aa[4][4];
    #pragma unroll
    for (int cc = 0; cc < 4; cc++) {
        #pragma unroll
        for (int hh = 0; hh < 2; hh++) {
            int k = 16 * cc + 2 * r + 8 * hh;
            Aa[cc][2 * hh]     = pack2(__float2half_rn(sx[k * MT + m0 + q]),
                                       __float2half_rn(sx[(k + 1) * MT + m0 + q]));
            Aa[cc][2 * hh + 1] = pack2(__float2half_rn(sx[k * MT + m0 + q + 8]),
                                       __float2half_rn(sx[(k + 1) * MT + m0 + q + 8]));
        }
    }

    // ---- phase 1: screening MMA, write fp16 scores to SMEM ----
    // score (pixel p, codes cb..cb+1) at byte SC_OFF + p*1024 + ((cb*2) ^ ((p&7)<<4))
    #pragma unroll 1
    for (int tg = 0; tg < 8; tg++) {
        const int t0 = wg * 32 + tg * 4;
        float acc[4][4];
        #pragma unroll
        for (int j = 0; j < 4; j++)
            #pragma unroll
            for (int c = 0; c < 4; c++) acc[j][c] = 0.0f;

        #pragma unroll
        for (int j = 0; j < 4; j++) {
            int n = (t0 + j) * 8 + q;
            const char* rowa = smem + BA_OFF + n * 128;
            int so = r + ((n & 1) << 2);
            uint4 va0 = *(const uint4*)(rowa + (so & 7) * 16);
            uint4 va1 = *(const uint4*)(rowa + ((so + 4) & 7) * 16);
            MMA_F16(acc[j], Aa[0][0], Aa[0][1], Aa[0][2], Aa[0][3], va0.x, va0.y);
            MMA_F16(acc[j], Aa[1][0], Aa[1][1], Aa[1][2], Aa[1][3], va0.z, va0.w);
            MMA_F16(acc[j], Aa[2][0], Aa[2][1], Aa[2][2], Aa[2][3], va1.x, va1.y);
            MMA_F16(acc[j], Aa[3][0], Aa[3][1], Aa[3][2], Aa[3][3], va1.z, va1.w);
        }
        #pragma unroll
        for (int j = 0; j < 4; j++) {
            int cb = (t0 + j) * 8 + 2 * r;
            float h0 = shes[cb], h1 = shes[cb + 1];
            __half2 ha = __floats2half2_rn(acc[j][0] - h0, acc[j][1] - h1);
            __half2 hb = __floats2half2_rn(acc[j][2] - h0, acc[j][3] - h1);
            int pa = m0 + q, pb = m0 + q + 8;
            int off = (cb << 1) ^ (q << 4);          // pa&7 == pb&7 == q
            *(uint32_t*)(smem + SC_OFF + pa * 1024 + off) = *(uint32_t*)&ha;
            *(uint32_t*)(smem + SC_OFF + pb * 1024 + off) = *(uint32_t*)&hb;
        }
    }
    __syncthreads();

    // ---- phase 2: per-pixel scan + certified exact rescore ----
    {
        const int p = tid >> 2, seg = tid & 3, p7 = p & 7;
        const char* rowp = smem + SC_OFF + p * 1024;

        // ||x||^2 for this pixel (quad-reduced)
        float xn2 = 0.0f;
        #pragma unroll
        for (int dd = 0; dd < 16; dd++) {
            float v = sx[(seg * 16 + dd) * MT + p];
            xn2 = fmaf(v, v, xn2);
        }
        xn2 += __shfl_xor_sync(0xffffffffu, xn2, 1);
        xn2 += __shfl_xor_sync(0xffffffffu, xn2, 2);

        // pass A: max of this segment's 128 scores
        __half2 m2 = __float2half2_rn(-65504.0f);
        #pragma unroll
        for (int c = 0; c < 16; c++) {
            int slot = ((seg << 4) + c) ^ p7;
            uint4 v = *(const uint4*)(rowp + slot * 16);
            __half2 h0 = *(__half2*)&v.x, h1 = *(__half2*)&v.y;
            __half2 h2 = *(__half2*)&v.z, h3 = *(__half2*)&v.w;
            m2 = __hmax2(m2, __hmax2(__hmax2(h0, h1), __hmax2(h2, h3)));
        }
        float smaxv = fmaxf(__low2float(m2), __high2float(m2));
        smaxv = fmaxf(smaxv, __shfl_xor_sync(0xffffffffu, smaxv, 1));
        smaxv = fmaxf(smaxv, __shfl_xor_sync(0xffffffffu, smaxv, 2));

        // rigorous margin: 2*(2^-10*1.05)*||x||*maxEn + fp16 store ulp slop
        float maxEn = sqrtf(2.0f * __int_as_float(g_mhbits));
        float marg = 2.2e-3f * sqrtf(xn2) * maxEn
                   + ldexpf(fmaxf(fabsf(smaxv), 1.0f), -9) + 2e-3f;
        float thr = smaxv - marg;
        __half thr_h = __float2half_rd(thr - 1e-3f);   // conservative quick-reject

        float bs = -FLT_MAX;
        int bi = 0x7fffffff;
        #pragma unroll 1
        for (int c = 0; c < 16; c++) {
            int slot = ((seg << 4) + c) ^ p7;
            uint4 v = *(const uint4*)(rowp + slot * 16);
            __half2 h[4] = {*(__half2*)&v.x, *(__half2*)&v.y,
                            *(__half2*)&v.z, *(__half2*)&v.w};
            __half2 mm = __hmax2(__hmax2(h[0], h[1]), __hmax2(h[2], h[3]));
            if (__hge(__hmax(__low2half(mm), __high2half(mm)), thr_h)) {
                int k0 = ((seg << 4) + c) * 8;
                #pragma unroll
                for (int w = 0; w < 4; w++) {
                    float2 f = __half22float2(h[w]);
                    #pragma unroll
                    for (int e = 0; e < 2; e++) {
                        float fv = (e == 0) ? f.x : f.y;
                        if (fv >= thr) {
                            int k = k0 + 2 * w + e;
                            const float4* er = (const float4*)(embed + (size_t)k * D);
                            float s = 0.0f;
                            #pragma unroll 4
                            for (int i = 0; i < 16; i++) {
                                float4 e4 = er[i];
                                s = fmaf(sx[(4 * i + 0) * MT + p], e4.x, s);
                                s = fmaf(sx[(4 * i + 1) * MT + p], e4.y, s);
                                s = fmaf(sx[(4 * i + 2) * MT + p], e4.z, s);
                                s = fmaf(sx[(4 * i + 3) * MT + p], e4.w, s);
                            }
                            s -= shes[k];
                            if (s > bs || (s == bs && k < bi)) { bs = s; bi = k; }
                        }
                    }
                }
            }
        }
        // merge the 4 segment lanes (ties -> smallest index)
        #pragma unroll
        for (int off = 1; off <= 2; off <<= 1) {
            float os = __shfl_xor_sync(0xffffffffu, bs, off);
            int   oi = __shfl_xor_sync(0xffffffffu, bi, off);
            if (os > bs || (os == bs && oi < bi)) { bs = os; bi = oi; }
        }
        if (seg == 0) sbest[p] = bi;
    }
    __syncthreads();

    // outputs: gathered codebook rows (NHWC) + indices (float)
    #pragma unroll
    for (int t = 0; t < 4; t++) {
        int i = tid + t * T;                      // MT*16 = 2048 float4 writes
        int j = i >> 4, c4 = i & 15;
        int idx = sbest[j];
        float4 v = *(const float4*)(embed + idx * D + (c4 << 2));
        *(float4*)(outq + ((size_t)(n0 + j)) * D + (c4 << 2)) = v;
    }
    if (outi && tid < MT) outi[n0 + tid] = (float)sbest[tid];
}

// ---------------------------------------------------------------------------
extern "C" void kernel_launch(void* const* d_in, const int* in_sizes, int n_in,
                              void* d_out, int out_size) {
    const float* x = (const float*)d_in[0];
    const float* embed = (const float*)d_in[1];
    float* out = (float*)d_out;

    const int N = in_sizes[0] / D;
    float* outi = nullptr;
    if (out_size >= N * D + N) outi = out + (size_t)N * D;

    cudaFuncSetAttribute(vq_main, cudaFuncAttributeMaxDynamicSharedMemorySize, SMEM_SZ);
    vq_prep<<<K, D>>>(embed);
    vq_main<<<N / MT, T, SMEM_SZ>>>(x, embed, out, outi);
}

// round 10
// speedup vs baseline: 1.1021x; 1.1021x over previous
#include <cuda_runtime.h>
#include <cuda_fp16.h>
#include <cstdint>
#include <cfloat>

// VQ R10: fp16 hi-pass tensor screen + certified exact fp32 rescore.
// vs R9: (1) approx max tracked in MMA-epilogue registers (pass A deleted),
// (2) seg-aware score swizzle -> conflict-free scan, (3) sbest folded into rows.

#define D    64
#define K    512
#define MT   128     // pixels per CTA
#define T    512     // threads per CTA (16 warps)

// SMEM layout (bytes)
#define SX_OFF    0                       // x tile fp32 [d][m]=[64][128]  32KB
#define BA_OFF    32768                   // codebook hi fp16 [512][128B]  64KB
#define SC_OFF    98304                   // scores fp16 [128][512]       128KB
#define SHES_OFF  229376                  // 512 f32
#define SAPX_OFF  231424                  // 128 u32 ordered approx-max
#define SMEM_SZ   231936

__device__ __half g_ea[K * D];   // fp16 hi split, permuted+swizzled rows
__device__ float  g_hes[K];      // 0.5*||e||^2
__device__ int    g_mhbits = 0;  // max hes as int bits (hes>0, monotone)

// ---------------- helpers ----------------
__device__ __forceinline__ uint32_t smem_u32(const void* p) {
    uint32_t a;
    asm("{ .reg .u64 t; cvta.to.shared.u64 t, %1; cvt.u32.u64 %0, t; }" : "=r"(a) : "l"(p));
    return a;
}
#define MMA_F16(c, a0, a1, a2, a3, b0, b1)                                       \
    asm volatile("mma.sync.aligned.m16n8k16.row.col.f32.f16.f16.f32 "            \
        "{%0,%1,%2,%3},{%4,%5,%6,%7},{%8,%9},{%0,%1,%2,%3};"                     \
        : "+f"((c)[0]), "+f"((c)[1]), "+f"((c)[2]), "+f"((c)[3])                  \
        : "r"(a0), "r"(a1), "r"(a2), "r"(a3), "r"(b0), "r"(b1))

__device__ __forceinline__ void cp16(uint32_t dst, const void* src) {
    asm volatile("cp.async.cg.shared.global [%0], [%1], 16;" :: "r"(dst), "l"(src) : "memory");
}
#define CP_COMMIT() asm volatile("cp.async.commit_group;" ::: "memory")
#define CP_WAIT(n)  asm volatile("cp.async.wait_group %0;" :: "n"(n) : "memory")

__device__ __forceinline__ uint32_t pack2(__half x, __half y) {
    __half2 h = __halves2half2(x, y);
    return *(uint32_t*)&h;
}
__device__ __forceinline__ unsigned ord_enc(float f) {
    unsigned u = __float_as_uint(f);
    return (u & 0x80000000u) ? ~u : (u | 0x80000000u);
}

// ---------------- prep: hi split codebook (permuted+swizzled), half norms ----
// element d = 32g+16c+8h+2rr+par -> slot ((g<<2)+rr+((k&1)<<2))&7, idx (2c+h)*2+par
__global__ void vq_prep(const float* __restrict__ embed) {
    int k = blockIdx.x, d = threadIdx.x;
    float v = embed[k * D + d];
    __half a = __float2half_rn(v);
    int g = d >> 5, kk = d & 31;
    int rr = (kk >> 1) & 3, h = (kk >> 3) & 1, c = (kk >> 4) & 1, par = kk & 1;
    int slot = ((g << 2) + rr + ((k & 1) << 2)) & 7;
    g_ea[k * 64 + slot * 8 + ((c << 1) + h) * 2 + par] = a;
    float s = v * v;
    #pragma unroll
    for (int o = 16; o > 0; o >>= 1) s += __shfl_down_sync(0xffffffffu, s, o);
    __shared__ float ws[2];
    if ((d & 31) == 0) ws[d >> 5] = s;
    __syncthreads();
    if (d == 0) {
        float hes = 0.5f * (ws[0] + ws[1]);
        g_hes[k] = hes;
        atomicMax(&g_mhbits, __float_as_int(hes));
    }
}

// ---------------- main ----------------
__global__ void __launch_bounds__(T, 1) vq_main(const float* __restrict__ x,
                                                const float* __restrict__ embed,
                                                float* __restrict__ outq,
                                                float* __restrict__ outi) {
    extern __shared__ __align__(1024) char smem[];
    uint32_t sb = smem_u32(smem);
    const int tid = threadIdx.x, wid = tid >> 5, lane = tid & 31;
    const int q = lane >> 2, r = lane & 3;
    const int wm = wid & 7;                  // m-group (16 pixels)
    const int wg = wid >> 3;                 // n-half (tiles 0..31 / 32..63)
    const int n0 = blockIdx.x * MT;
    const int b = n0 >> 12, hw0 = n0 & 4095;

    float* sx = (float*)(smem + SX_OFF);     // [d][128]
    float* shes = (float*)(smem + SHES_OFF);
    unsigned* sapx = (unsigned*)(smem + SAPX_OFF);

    // stage hi codebook (64KB) via cp.async
    #pragma unroll
    for (int t = 0; t < 8; t++) {
        int c = tid + t * T;                 // 4096 16B chunks
        cp16(sb + BA_OFF + c * 16, (const char*)g_ea + c * 16);
    }
    CP_COMMIT();

    // stage x tile: sx[c][j] = x[b][c][hw0+j]
    #pragma unroll
    for (int t = 0; t < 4; t++) {
        int i = tid + t * T;
        int c = i >> 5, j4 = (i & 31) << 2;
        float4 v = *(const float4*)(x + (((size_t)(b * D + c)) << 12) + hw0 + j4);
        *(float4*)(sx + c * MT + j4) = v;
    }
    shes[tid] = g_hes[tid];
    if (tid < MT) sapx[tid] = 0u;
    CP_WAIT(0);
    __syncthreads();

    // A hi fragments: rows m0+q, m0+q+8; Aa[cc][reg], k-lo = 16cc+2r (+8 for hi regs)
    const int m0 = wm * 16;
    uint32_t Aa[4][4];
    #pragma unroll
    for (int cc = 0; cc < 4; cc++) {
        #pragma unroll
        for (int hh = 0; hh < 2; hh++) {
            int k = 16 * cc + 2 * r + 8 * hh;
            Aa[cc][2 * hh]     = pack2(__float2half_rn(sx[k * MT + m0 + q]),
                                       __float2half_rn(sx[(k + 1) * MT + m0 + q]));
            Aa[cc][2 * hh + 1] = pack2(__float2half_rn(sx[k * MT + m0 + q + 8]),
                                       __float2half_rn(sx[(k + 1) * MT + m0 + q + 8]));
        }
    }

    // ---- phase 1: screening MMA; write fp16 scores + track per-pixel max ----
    // score row p (1024B = 64 slots); logical slot L = code>>3 stored at
    // physical slot L ^ (p&7) ^ ((L>>4)<<1)  -> writer & scanner conflict-free
    const int pa = m0 + q, pb = m0 + q + 8;
    float mx0 = -FLT_MAX, mx1 = -FLT_MAX;

    #pragma unroll 1
    for (int tg = 0; tg < 8; tg++) {
        const int t0 = wg * 32 + tg * 4;
        float acc[4][4];
        #pragma unroll
        for (int j = 0; j < 4; j++)
            #pragma unroll
            for (int c = 0; c < 4; c++) acc[j][c] = 0.0f;

        #pragma unroll
        for (int j = 0; j < 4; j++) {
            int n = (t0 + j) * 8 + q;
            const char* rowa = smem + BA_OFF + n * 128;
            int so = r + ((n & 1) << 2);
            uint4 va0 = *(const uint4*)(rowa + (so & 7) * 16);
            uint4 va1 = *(const uint4*)(rowa + ((so + 4) & 7) * 16);
            MMA_F16(acc[j], Aa[0][0], Aa[0][1], Aa[0][2], Aa[0][3], va0.x, va0.y);
            MMA_F16(acc[j], Aa[1][0], Aa[1][1], Aa[1][2], Aa[1][3], va0.z, va0.w);
            MMA_F16(acc[j], Aa[2][0], Aa[2][1], Aa[2][2], Aa[2][3], va1.x, va1.y);
            MMA_F16(acc[j], Aa[3][0], Aa[3][1], Aa[3][2], Aa[3][3], va1.z, va1.w);
        }
        #pragma unroll
        for (int j = 0; j < 4; j++) {
            int L = t0 + j;                      // logical slot, codes 8L..8L+7
            int cb = L * 8 + 2 * r;
            float h0 = shes[cb], h1 = shes[cb + 1];
            float s00 = acc[j][0] - h0, s01 = acc[j][1] - h1;
            float s10 = acc[j][2] - h0, s11 = acc[j][3] - h1;
            mx0 = fmaxf(mx0, fmaxf(s00, s01));
            mx1 = fmaxf(mx1, fmaxf(s10, s11));
            __half2 ha = __floats2half2_rn(s00, s01);
            __half2 hb = __floats2half2_rn(s10, s11);
            int ps = L ^ q ^ ((L >> 4) << 1);    // p&7 == q for both pa, pb
            int off = ps * 16 + 4 * r;
            *(uint32_t*)(smem + SC_OFF + pa * 1024 + off) = *(uint32_t*)&ha;
            *(uint32_t*)(smem + SC_OFF + pb * 1024 + off) = *(uint32_t*)&hb;
        }
    }
    // quad-reduce max over r lanes, publish per-pixel ordered max
    mx0 = fmaxf(mx0, __shfl_xor_sync(0xffffffffu, mx0, 1));
    mx0 = fmaxf(mx0, __shfl_xor_sync(0xffffffffu, mx0, 2));
    mx1 = fmaxf(mx1, __shfl_xor_sync(0xffffffffu, mx1, 1));
    mx1 = fmaxf(mx1, __shfl_xor_sync(0xffffffffu, mx1, 2));
    if (r == 0) {
        atomicMax(&sapx[pa], ord_enc(mx0));
        atomicMax(&sapx[pb], ord_enc(mx1));
    }
    __syncthreads();

    // ---- phase 2: per-pixel candidate scan + certified exact rescore ----
    {
        const int p = tid >> 2, seg = tid & 3, p7 = p & 7;
        const char* rowp = smem + SC_OFF + p * 1024;

        // ||x||^2 for this pixel (quad-reduced)
        float xn2 = 0.0f;
        #pragma unroll
        for (int dd = 0; dd < 16; dd++) {
            float v = sx[(seg * 16 + dd) * MT + p];
            xn2 = fmaf(v, v, xn2);
        }
        xn2 += __shfl_xor_sync(0xffffffffu, xn2, 1);
        xn2 += __shfl_xor_sync(0xffffffffu, xn2, 2);

        // decode pixel approx max
        unsigned u = sapx[p];
        float smaxv = __uint_as_float((u & 0x80000000u) ? (u & 0x7fffffffu) : ~u);

        // rigorous margin: 2*(2^-10*1.05)*||x||*maxEn + fp16 store ulp slop
        float maxEn = sqrtf(2.0f * __int_as_float(g_mhbits));
        float marg = 2.2e-3f * sqrtf(xn2) * maxEn
                   + ldexpf(fmaxf(fabsf(smaxv), 1.0f), -9) + 2e-3f;
        float thr = smaxv - marg;
        __half thr_h = __float2half_rd(thr - 1e-3f);   // conservative quick-reject

        float bs = -FLT_MAX;
        int bi = 0x7fffffff;
        #pragma unroll 1
        for (int c = 0; c < 16; c++) {
            int L = (seg << 4) + c;
            int slot = L ^ p7 ^ (seg << 1);
            uint4 v = *(const uint4*)(rowp + slot * 16);
            __half2 h[4] = {*(__half2*)&v.x, *(__half2*)&v.y,
                            *(__half2*)&v.z, *(__half2*)&v.w};
            __half2 mm = __hmax2(__hmax2(h[0], h[1]), __hmax2(h[2], h[3]));
            if (__hge(__hmax(__low2half(mm), __high2half(mm)), thr_h)) {
                int k0 = L * 8;
                #pragma unroll
                for (int w = 0; w < 4; w++) {
                    float2 f = __half22float2(h[w]);
                    #pragma unroll
                    for (int e = 0; e < 2; e++) {
                        float fv = (e == 0) ? f.x : f.y;
                        if (fv >= thr) {
                            int k = k0 + 2 * w + e;
                            const float4* er = (const float4*)(embed + (size_t)k * D);
                            float s = 0.0f;
                            #pragma unroll 4
                            for (int i = 0; i < 16; i++) {
                                float4 e4 = er[i];
                                s = fmaf(sx[(4 * i + 0) * MT + p], e4.x, s);
                                s = fmaf(sx[(4 * i + 1) * MT + p], e4.y, s);
                                s = fmaf(sx[(4 * i + 2) * MT + p], e4.z, s);
                                s = fmaf(sx[(4 * i + 3) * MT + p], e4.w, s);
                            }
                            s -= shes[k];
                            if (s > bs || (s == bs && k < bi)) { bs = s; bi = k; }
                        }
                    }
                }
            }
        }
        // merge the 4 segment lanes (ties -> smallest index)
        #pragma unroll
        for (int off = 1; off <= 2; off <<= 1) {
            float os = __shfl_xor_sync(0xffffffffu, bs, off);
            int   oi = __shfl_xor_sync(0xffffffffu, bi, off);
            if (os > bs || (os == bs && oi < bi)) { bs = os; bi = oi; }
        }
        // park the winner at byte 0 of this pixel's (now-dead) score row
        if (seg == 0) *(int*)(smem + SC_OFF + p * 1024) = bi;
    }
    __syncthreads();

    // outputs: gathered codebook rows (NHWC) + indices (float)
    #pragma unroll
    for (int t = 0; t < 4; t++) {
        int i = tid + t * T;                      // MT*16 = 2048 float4 writes
        int j = i >> 4, c4 = i & 15;
        int idx = *(const int*)(smem + SC_OFF + j * 1024);
        float4 v = *(const float4*)(embed + idx * D + (c4 << 2));
        *(float4*)(outq + ((size_t)(n0 + j)) * D + (c4 << 2)) = v;
    }
    if (outi && tid < MT)
        outi[n0 + tid] = (float)(*(const int*)(smem + SC_OFF + tid * 1024));
}

// ---------------------------------------------------------------------------
extern "C" void kernel_launch(void* const* d_in, const int* in_sizes, int n_in,
                              void* d_out, int out_size) {
    const float* x = (const float*)d_in[0];
    const float* embed = (const float*)d_in[1];
    float* out = (float*)d_out;

    const int N = in_sizes[0] / D;
    float* outi = nullptr;
    if (out_size >= N * D + N) outi = out + (size_t)N * D;

    cudaFuncSetAttribute(vq_main, cudaFuncAttributeMaxDynamicSharedMemorySize, SMEM_SZ);
    vq_prep<<<K, D>>>(embed);
    vq_main<<<N / MT, T, SMEM_SZ>>>(x, embed, out, outi);
}

// round 11
// speedup vs baseline: 1.3949x; 1.2657x over previous
#include <cuda_runtime.h>
#include <cuda_fp16.h>
#include <cstdint>
#include <cfloat>

// VQ R11: fp16 hi-pass tensor screen + certified exact fp32 rescore.
// vs R10: branch-free mask-based scan (no BSSY/BSYNC per iter), ffs candidate
// walk, ||x||^2 folded into the A-fragment loader (conflicted pass deleted).

#define D    64
#define K    512
#define MT   128     // pixels per CTA
#define T    512     // threads per CTA (16 warps)

// SMEM layout (bytes)
#define SX_OFF    0                       // x tile fp32 [d][m]=[64][128]  32KB
#define BA_OFF    32768                   // codebook hi fp16 [512][128B]  64KB
#define SC_OFF    98304                   // scores fp16 [128][512]       128KB
#define SHES_OFF  229376                  // 512 f32
#define SAPX_OFF  231424                  // 128 u32 ordered approx-max
#define SNORM_OFF 231936                  // 128 f32 ||x||^2
#define SMEM_SZ   232448

__device__ __half g_ea[K * D];   // fp16 hi split, permuted+swizzled rows
__device__ float  g_hes[K];      // 0.5*||e||^2
__device__ int    g_mhbits = 0;  // max hes as int bits (hes>0, monotone)

// ---------------- helpers ----------------
__device__ __forceinline__ uint32_t smem_u32(const void* p) {
    uint32_t a;
    asm("{ .reg .u64 t; cvta.to.shared.u64 t, %1; cvt.u32.u64 %0, t; }" : "=r"(a) : "l"(p));
    return a;
}
#define MMA_F16(c, a0, a1, a2, a3, b0, b1)                                       \
    asm volatile("mma.sync.aligned.m16n8k16.row.col.f32.f16.f16.f32 "            \
        "{%0,%1,%2,%3},{%4,%5,%6,%7},{%8,%9},{%0,%1,%2,%3};"                     \
        : "+f"((c)[0]), "+f"((c)[1]), "+f"((c)[2]), "+f"((c)[3])                  \
        : "r"(a0), "r"(a1), "r"(a2), "r"(a3), "r"(b0), "r"(b1))

__device__ __forceinline__ void cp16(uint32_t dst, const void* src) {
    asm volatile("cp.async.cg.shared.global [%0], [%1], 16;" :: "r"(dst), "l"(src) : "memory");
}
#define CP_COMMIT() asm volatile("cp.async.commit_group;" ::: "memory")
#define CP_WAIT(n)  asm volatile("cp.async.wait_group %0;" :: "n"(n) : "memory")

__device__ __forceinline__ uint32_t pack2(__half x, __half y) {
    __half2 h = __halves2half2(x, y);
    return *(uint32_t*)&h;
}
__device__ __forceinline__ unsigned ord_enc(float f) {
    unsigned u = __float_as_uint(f);
    return (u & 0x80000000u) ? ~u : (u | 0x80000000u);
}

// exact fp32 rescore: x_p . e_k - 0.5||e_k||^2 (4 independent FMA chains)
__device__ __forceinline__ float rescore(const float* __restrict__ embed,
                                          const float* __restrict__ sx,
                                          const float* __restrict__ shes,
                                          int p, int k) {
    const float4* er = (const float4*)(embed + (size_t)k * D);
    float s0 = 0.f, s1 = 0.f, s2 = 0.f, s3 = 0.f;
    #pragma unroll
    for (int i = 0; i < 16; i++) {
        float4 e4 = er[i];
        s0 = fmaf(sx[(4 * i + 0) * MT + p], e4.x, s0);
        s1 = fmaf(sx[(4 * i + 1) * MT + p], e4.y, s1);
        s2 = fmaf(sx[(4 * i + 2) * MT + p], e4.z, s2);
        s3 = fmaf(sx[(4 * i + 3) * MT + p], e4.w, s3);
    }
    return ((s0 + s1) + (s2 + s3)) - shes[k];
}

// ---------------- prep: hi split codebook (permuted+swizzled), half norms ----
// element d = 32g+16c+8h+2rr+par -> slot ((g<<2)+rr+((k&1)<<2))&7, idx (2c+h)*2+par
__global__ void vq_prep(const float* __restrict__ embed) {
    int k = blockIdx.x, d = threadIdx.x;
    float v = embed[k * D + d];
    __half a = __float2half_rn(v);
    int g = d >> 5, kk = d & 31;
    int rr = (kk >> 1) & 3, h = (kk >> 3) & 1, c = (kk >> 4) & 1, par = kk & 1;
    int slot = ((g << 2) + rr + ((k & 1) << 2)) & 7;
    g_ea[k * 64 + slot * 8 + ((c << 1) + h) * 2 + par] = a;
    float s = v * v;
    #pragma unroll
    for (int o = 16; o > 0; o >>= 1) s += __shfl_down_sync(0xffffffffu, s, o);
    __shared__ float ws[2];
    if ((d & 31) == 0) ws[d >> 5] = s;
    __syncthreads();
    if (d == 0) {
        float hes = 0.5f * (ws[0] + ws[1]);
        g_hes[k] = hes;
        atomicMax(&g_mhbits, __float_as_int(hes));
    }
}

// ---------------- main ----------------
__global__ void __launch_bounds__(T, 1) vq_main(const float* __restrict__ x,
                                                const float* __restrict__ embed,
                                                float* __restrict__ outq,
                                                float* __restrict__ outi) {
    extern __shared__ __align__(1024) char smem[];
    uint32_t sb = smem_u32(smem);
    const int tid = threadIdx.x, wid = tid >> 5, lane = tid & 31;
    const int q = lane >> 2, r = lane & 3;
    const int wm = wid & 7;                  // m-group (16 pixels)
    const int wg = wid >> 3;                 // n-half (tiles 0..31 / 32..63)
    const int n0 = blockIdx.x * MT;
    const int b = n0 >> 12, hw0 = n0 & 4095;

    float* sx = (float*)(smem + SX_OFF);     // [d][128]
    float* shes = (float*)(smem + SHES_OFF);
    unsigned* sapx = (unsigned*)(smem + SAPX_OFF);
    float* snorm = (float*)(smem + SNORM_OFF);

    // stage hi codebook (64KB) via cp.async
    #pragma unroll
    for (int t = 0; t < 8; t++) {
        int c = tid + t * T;                 // 4096 16B chunks
        cp16(sb + BA_OFF + c * 16, (const char*)g_ea + c * 16);
    }
    CP_COMMIT();

    // stage x tile: sx[c][j] = x[b][c][hw0+j]
    #pragma unroll
    for (int t = 0; t < 4; t++) {
        int i = tid + t * T;
        int c = i >> 5, j4 = (i & 31) << 2;
        float4 v = *(const float4*)(x + (((size_t)(b * D + c)) << 12) + hw0 + j4);
        *(float4*)(sx + c * MT + j4) = v;
    }
    shes[tid] = g_hes[tid];
    if (tid < MT) sapx[tid] = 0u;
    CP_WAIT(0);
    __syncthreads();

    // A hi fragments + ||x||^2 partials (values already in registers)
    const int m0 = wm * 16;
    const int pa = m0 + q, pb = m0 + q + 8;
    uint32_t Aa[4][4];
    float xp0 = 0.f, xp1 = 0.f;
    #pragma unroll
    for (int cc = 0; cc < 4; cc++) {
        #pragma unroll
        for (int hh = 0; hh < 2; hh++) {
            int k = 16 * cc + 2 * r + 8 * hh;
            float f0a = sx[k * MT + m0 + q],     f1a = sx[(k + 1) * MT + m0 + q];
            float f0b = sx[k * MT + m0 + q + 8], f1b = sx[(k + 1) * MT + m0 + q + 8];
            xp0 = fmaf(f0a, f0a, fmaf(f1a, f1a, xp0));
            xp1 = fmaf(f0b, f0b, fmaf(f1b, f1b, xp1));
            Aa[cc][2 * hh]     = pack2(__float2half_rn(f0a), __float2half_rn(f1a));
            Aa[cc][2 * hh + 1] = pack2(__float2half_rn(f0b), __float2half_rn(f1b));
        }
    }
    xp0 += __shfl_xor_sync(0xffffffffu, xp0, 1);
    xp0 += __shfl_xor_sync(0xffffffffu, xp0, 2);
    xp1 += __shfl_xor_sync(0xffffffffu, xp1, 1);
    xp1 += __shfl_xor_sync(0xffffffffu, xp1, 2);
    if (r == 0 && wg == 0) { snorm[pa] = xp0; snorm[pb] = xp1; }

    // ---- phase 1: screening MMA; write fp16 scores + track per-pixel max ----
    // score row p (1024B = 64 slots); logical slot L = code>>3 stored at
    // physical slot L ^ (p&7) ^ ((L>>4)<<1)  -> writer & scanner conflict-free
    float mx0 = -FLT_MAX, mx1 = -FLT_MAX;

    #pragma unroll 1
    for (int tg = 0; tg < 8; tg++) {
        const int t0 = wg * 32 + tg * 4;
        float acc[4][4];
        #pragma unroll
        for (int j = 0; j < 4; j++)
            #pragma unroll
            for (int c = 0; c < 4; c++) acc[j][c] = 0.0f;

        #pragma unroll
        for (int j = 0; j < 4; j++) {
            int n = (t0 + j) * 8 + q;
            const char* rowa = smem + BA_OFF + n * 128;
            int so = r + ((n & 1) << 2);
            uint4 va0 = *(const uint4*)(rowa + (so & 7) * 16);
            uint4 va1 = *(const uint4*)(rowa + ((so + 4) & 7) * 16);
            MMA_F16(acc[j], Aa[0][0], Aa[0][1], Aa[0][2], Aa[0][3], va0.x, va0.y);
            MMA_F16(acc[j], Aa[1][0], Aa[1][1], Aa[1][2], Aa[1][3], va0.z, va0.w);
            MMA_F16(acc[j], Aa[2][0], Aa[2][1], Aa[2][2], Aa[2][3], va1.x, va1.y);
            MMA_F16(acc[j], Aa[3][0], Aa[3][1], Aa[3][2], Aa[3][3], va1.z, va1.w);
        }
        #pragma unroll
        for (int j = 0; j < 4; j++) {
            int L = t0 + j;                      // logical slot, codes 8L..8L+7
            int cb = L * 8 + 2 * r;
            float h0 = shes[cb], h1 = shes[cb + 1];
            float s00 = acc[j][0] - h0, s01 = acc[j][1] - h1;
            float s10 = acc[j][2] - h0, s11 = acc[j][3] - h1;
            mx0 = fmaxf(mx0, fmaxf(s00, s01));
            mx1 = fmaxf(mx1, fmaxf(s10, s11));
            __half2 ha = __floats2half2_rn(s00, s01);
            __half2 hb = __floats2half2_rn(s10, s11);
            int ps = L ^ q ^ ((L >> 4) << 1);    // p&7 == q for both pa, pb
            int off = ps * 16 + 4 * r;
            *(uint32_t*)(smem + SC_OFF + pa * 1024 + off) = *(uint32_t*)&ha;
            *(uint32_t*)(smem + SC_OFF + pb * 1024 + off) = *(uint32_t*)&hb;
        }
    }
    // quad-reduce max over r lanes, publish per-pixel ordered max
    mx0 = fmaxf(mx0, __shfl_xor_sync(0xffffffffu, mx0, 1));
    mx0 = fmaxf(mx0, __shfl_xor_sync(0xffffffffu, mx0, 2));
    mx1 = fmaxf(mx1, __shfl_xor_sync(0xffffffffu, mx1, 1));
    mx1 = fmaxf(mx1, __shfl_xor_sync(0xffffffffu, mx1, 2));
    if (r == 0) {
        atomicMax(&sapx[pa], ord_enc(mx0));
        atomicMax(&sapx[pb], ord_enc(mx1));
    }
    __syncthreads();

    // ---- phase 2: branch-free candidate scan + certified exact rescore ----
    {
        const int p = tid >> 2, seg = tid & 3, p7 = p & 7;
        const char* rowp = smem + SC_OFF + p * 1024;

        unsigned u = sapx[p];
        float smaxv = __uint_as_float((u & 0x80000000u) ? (u & 0x7fffffffu) : ~u);

        // rigorous margin: 2*(2^-10*1.05)*||x||*maxEn + fp16 store ulp slop
        float maxEn = sqrtf(2.0f * __int_as_float(g_mhbits));
        float marg = 2.2e-3f * sqrtf(snorm[p]) * maxEn
                   + ldexpf(fmaxf(fabsf(smaxv), 1.0f), -9) + 2e-3f;
        float thr = smaxv - marg;
        __half thr_h = __float2half_rd(thr);

        // branch-free scan: bit c set if 8-code group c may contain a candidate
        unsigned mask = 0;
        #pragma unroll
        for (int c = 0; c < 16; c++) {
            int slot = ((seg << 4) + c) ^ p7 ^ (seg << 1);
            uint4 v = *(const uint4*)(rowp + slot * 16);
            __half2 h0 = *(__half2*)&v.x, h1 = *(__half2*)&v.y;
            __half2 h2 = *(__half2*)&v.z, h3 = *(__half2*)&v.w;
            __half2 mm = __hmax2(__hmax2(h0, h1), __hmax2(h2, h3));
            __half m = __hmax(__low2half(mm), __high2half(mm));
            mask |= ((unsigned)__hge(m, thr_h)) << c;
        }

        float bs = -FLT_MAX;
        int bi = 0x7fffffff;
        while (mask) {
            int c = __ffs(mask) - 1;
            mask &= mask - 1;
            int L = (seg << 4) + c;
            int slot = L ^ p7 ^ (seg << 1);
            uint4 v = *(const uint4*)(rowp + slot * 16);
            const __half2* h2 = (const __half2*)&v;
            #pragma unroll
            for (int w = 0; w < 4; w++) {
                float2 f = __half22float2(h2[w]);
                if (f.x >= thr) {
                    int k = L * 8 + 2 * w;
                    float s = rescore(embed, sx, shes, p, k);
                    if (s > bs || (s == bs && k < bi)) { bs = s; bi = k; }
                }
                if (f.y >= thr) {
                    int k = L * 8 + 2 * w + 1;
                    float s = rescore(embed, sx, shes, p, k);
                    if (s > bs || (s == bs && k < bi)) { bs = s; bi = k; }
                }
            }
        }
        // merge the 4 segment lanes (ties -> smallest index)
        #pragma unroll
        for (int off = 1; off <= 2; off <<= 1) {
            float os = __shfl_xor_sync(0xffffffffu, bs, off);
            int   oi = __shfl_xor_sync(0xffffffffu, bi, off);
            if (os > bs || (os == bs && oi < bi)) { bs = os; bi = oi; }
        }
        // park the winner at byte 0 of this pixel's (now-dead) score row
        if (seg == 0) *(int*)(smem + SC_OFF + p * 1024) = bi;
    }
    __syncthreads();

    // outputs: gathered codebook rows (NHWC) + indices (float)
    #pragma unroll
    for (int t = 0; t < 4; t++) {
        int i = tid + t * T;                      // MT*16 = 2048 float4 writes
        int j = i >> 4, c4 = i & 15;
        int idx = *(const int*)(smem + SC_OFF + j * 1024);
        float4 v = *(const float4*)(embed + idx * D + (c4 << 2));
        *(float4*)(outq + ((size_t)(n0 + j)) * D + (c4 << 2)) = v;
    }
    if (outi && tid < MT)
        outi[n0 + tid] = (float)(*(const int*)(smem + SC_OFF + tid * 1024));
}

// ---------------------------------------------------------------------------
extern "C" void kernel_launch(void* const* d_in, const int* in_sizes, int n_in,
                              void* d_out, int out_size) {
    const float* x = (const float*)d_in[0];
    const float* embed = (const float*)d_in[1];
    float* out = (float*)d_out;

    const int N = in_sizes[0] / D;
    float* outi = nullptr;
    if (out_size >= N * D + N) outi = out + (size_t)N * D;

    cudaFuncSetAttribute(vq_main, cudaFuncAttributeMaxDynamicSharedMemorySize, SMEM_SZ);
    vq_prep<<<K, D>>>(embed);
    vq_main<<<N / MT, T, SMEM_SZ>>>(x, embed, out, outi);
}

// round 12
// speedup vs baseline: 1.4212x; 1.0188x over previous
#include <cuda_runtime.h>
#include <cuda_fp16.h>
#include <cstdint>
#include <cfloat>

// VQ R12: screen-recompute. Phase A: fp16 hi-pass MMA, per-pixel max in regs.
// Phase B: re-run identical MMAs, push codes >= certified threshold to a list.
// Phase C: exact fp32 rescore of candidates. No score buffer -> 107KB SMEM
// -> 2 CTAs/SM (16 warps) -> tensor pipe becomes the binding resource.

#define D    64
#define K    512
#define MT   128     // pixels per CTA
#define T    256     // threads per CTA (8 warps), 2 CTAs/SM
#define SXS  140     // padded sx row stride (floats): conflict-free frag loads
#define CAP  1024    // candidate list capacity (expected ~166)

// SMEM layout (bytes) — total 109584 (~107KB) => 2 CTAs/SM
#define SX_OFF    0                       // x tile fp32 [d][SXS]        35840
#define BA_OFF    35840                   // codebook hi fp16 [512][128] 65536
#define SHES_OFF  101376                  // 512 f32
#define SAPX_OFF  103424                  // 128 u32 ordered approx-max
#define SNORM_OFF 103936                  // 128 f32 ||x||^2
#define SBEST_OFF 104448                  // 128 u64 exact best
#define CNT_OFF   105472                  // int counter (+pad)
#define LIST_OFF  105488                  // CAP u32 candidates
#define SMEM_SZ   109584

__device__ __half g_ea[K * D];   // fp16 hi split, permuted+swizzled rows
__device__ float  g_hes[K];      // 0.5*||e||^2
__device__ int    g_mhbits = 0;  // max hes as int bits

// ---------------- helpers ----------------
__device__ __forceinline__ uint32_t smem_u32(const void* p) {
    uint32_t a;
    asm("{ .reg .u64 t; cvta.to.shared.u64 t, %1; cvt.u32.u64 %0, t; }" : "=r"(a) : "l"(p));
    return a;
}
#define MMA_F16(c, a0, a1, a2, a3, b0, b1)                                       \
    asm volatile("mma.sync.aligned.m16n8k16.row.col.f32.f16.f16.f32 "            \
        "{%0,%1,%2,%3},{%4,%5,%6,%7},{%8,%9},{%0,%1,%2,%3};"                     \
        : "+f"((c)[0]), "+f"((c)[1]), "+f"((c)[2]), "+f"((c)[3])                  \
        : "r"(a0), "r"(a1), "r"(a2), "r"(a3), "r"(b0), "r"(b1))

__device__ __forceinline__ void cp16(uint32_t dst, const void* src) {
    asm volatile("cp.async.cg.shared.global [%0], [%1], 16;" :: "r"(dst), "l"(src) : "memory");
}
#define CP_COMMIT() asm volatile("cp.async.commit_group;" ::: "memory")
#define CP_WAIT(n)  asm volatile("cp.async.wait_group %0;" :: "n"(n) : "memory")

__device__ __forceinline__ uint32_t pack2(__half x, __half y) {
    __half2 h = __halves2half2(x, y);
    return *(uint32_t*)&h;
}
__device__ __forceinline__ unsigned ord_enc(float f) {
    unsigned u = __float_as_uint(f);
    return (u & 0x80000000u) ? ~u : (u | 0x80000000u);
}

// exact fp32 rescore: x_p . e_k - 0.5||e_k||^2 (4 independent FMA chains)
__device__ __forceinline__ float rescore(const float* __restrict__ embed,
                                          const float* __restrict__ sx,
                                          const float* __restrict__ shes,
                                          int p, int k) {
    const float4* er = (const float4*)(embed + (size_t)k * D);
    float s0 = 0.f, s1 = 0.f, s2 = 0.f, s3 = 0.f;
    #pragma unroll
    for (int i = 0; i < 16; i++) {
        float4 e4 = er[i];
        s0 = fmaf(sx[(4 * i + 0) * SXS + p], e4.x, s0);
        s1 = fmaf(sx[(4 * i + 1) * SXS + p], e4.y, s1);
        s2 = fmaf(sx[(4 * i + 2) * SXS + p], e4.z, s2);
        s3 = fmaf(sx[(4 * i + 3) * SXS + p], e4.w, s3);
    }
    return ((s0 + s1) + (s2 + s3)) - shes[k];
}

// ---------------- prep: hi split codebook (permuted+swizzled), half norms ----
// element d = 32g+16c+8h+2rr+par -> slot ((g<<2)+rr+((k&1)<<2))&7, idx (2c+h)*2+par
__global__ void vq_prep(const float* __restrict__ embed) {
    int k = blockIdx.x, d = threadIdx.x;
    float v = embed[k * D + d];
    __half a = __float2half_rn(v);
    int g = d >> 5, kk = d & 31;
    int rr = (kk >> 1) & 3, h = (kk >> 3) & 1, c = (kk >> 4) & 1, par = kk & 1;
    int slot = ((g << 2) + rr + ((k & 1) << 2)) & 7;
    g_ea[k * 64 + slot * 8 + ((c << 1) + h) * 2 + par] = a;
    float s = v * v;
    #pragma unroll
    for (int o = 16; o > 0; o >>= 1) s += __shfl_down_sync(0xffffffffu, s, o);
    __shared__ float ws[2];
    if ((d & 31) == 0) ws[d >> 5] = s;
    __syncthreads();
    if (d == 0) {
        float hes = 0.5f * (ws[0] + ws[1]);
        g_hes[k] = hes;
        atomicMax(&g_mhbits, __float_as_int(hes));
    }
}

// ---------------- main ----------------
__global__ void __launch_bounds__(T, 2) vq_main(const float* __restrict__ x,
                                                const float* __restrict__ embed,
                                                float* __restrict__ outq,
                                                float* __restrict__ outi) {
    extern __shared__ __align__(128) char smem[];
    uint32_t sb = smem_u32(smem);
    const int tid = threadIdx.x, wid = tid >> 5, lane = tid & 31;
    const int q = lane >> 2, r = lane & 3;
    const int wm = wid >> 1;                 // m-quarter (32 pixels, 2 m-tiles)
    const int ng = wid & 1;                  // n-half (256 codes, 32 tiles)
    const int n0 = blockIdx.x * MT;
    const int b = n0 >> 12, hw0 = n0 & 4095;

    float* sx = (float*)(smem + SX_OFF);     // [d][SXS]
    float* shes = (float*)(smem + SHES_OFF);
    unsigned* sapx = (unsigned*)(smem + SAPX_OFF);
    float* snorm = (float*)(smem + SNORM_OFF);
    unsigned long long* sbest = (unsigned long long*)(smem + SBEST_OFF);
    int* scnt = (int*)(smem + CNT_OFF);
    unsigned* slist = (unsigned*)(smem + LIST_OFF);

    // stage hi codebook (64KB) via cp.async
    #pragma unroll
    for (int t = 0; t < 16; t++) {
        int c = tid + t * T;                 // 4096 16B chunks
        cp16(sb + BA_OFF + c * 16, (const char*)g_ea + c * 16);
    }
    CP_COMMIT();

    // stage x tile: sx[c][j] = x[b][c][hw0+j] (padded stride SXS)
    #pragma unroll
    for (int t = 0; t < 8; t++) {
        int i = tid + t * T;
        int c = i >> 5, j4 = (i & 31) << 2;
        float4 v = *(const float4*)(x + (((size_t)(b * D + c)) << 12) + hw0 + j4);
        *(float4*)(sx + c * SXS + j4) = v;
    }
    shes[tid] = g_hes[tid];
    shes[tid + 256] = g_hes[tid + 256];
    if (tid < MT) { sapx[tid] = 0u; sbest[tid] = 0ull; }
    if (tid == 0) *scnt = 0;
    CP_WAIT(0);
    __syncthreads();

    // A hi fragments for 2 m-tiles + ||x||^2 partials
    const int m0 = wm * 32;
    uint32_t Aa[2][4][4];
    float xp[4] = {0.f, 0.f, 0.f, 0.f};
    #pragma unroll
    for (int mt = 0; mt < 2; mt++) {
        #pragma unroll
        for (int cc = 0; cc < 4; cc++) {
            #pragma unroll
            for (int hh = 0; hh < 2; hh++) {
                int k = 16 * cc + 8 * hh + 2 * r;
                int r0 = m0 + mt * 16 + q;
                float f0a = sx[k * SXS + r0],     f1a = sx[(k + 1) * SXS + r0];
                float f0b = sx[k * SXS + r0 + 8], f1b = sx[(k + 1) * SXS + r0 + 8];
                xp[2 * mt]     = fmaf(f0a, f0a, fmaf(f1a, f1a, xp[2 * mt]));
                xp[2 * mt + 1] = fmaf(f0b, f0b, fmaf(f1b, f1b, xp[2 * mt + 1]));
                Aa[mt][cc][2 * hh]     = pack2(__float2half_rn(f0a), __float2half_rn(f1a));
                Aa[mt][cc][2 * hh + 1] = pack2(__float2half_rn(f0b), __float2half_rn(f1b));
            }
        }
    }
    #pragma unroll
    for (int i = 0; i < 4; i++) {
        xp[i] += __shfl_xor_sync(0xffffffffu, xp[i], 1);
        xp[i] += __shfl_xor_sync(0xffffffffu, xp[i], 2);
    }
    if (r == 0 && ng == 0) {
        snorm[m0 + q] = xp[0];      snorm[m0 + q + 8] = xp[1];
        snorm[m0 + 16 + q] = xp[2]; snorm[m0 + 24 + q] = xp[3];
    }

    // ---- phase A: screen MMA, track per-thread max per row ----
    float mx[4] = {-FLT_MAX, -FLT_MAX, -FLT_MAX, -FLT_MAX};
    #pragma unroll 1
    for (int G = 0; G < 8; G++) {
        float acc[2][4][4];
        #pragma unroll
        for (int mt = 0; mt < 2; mt++)
            #pragma unroll
            for (int j = 0; j < 4; j++)
                #pragma unroll
                for (int c = 0; c < 4; c++) acc[mt][j][c] = 0.f;
        #pragma unroll
        for (int j = 0; j < 4; j++) {
            int n = (ng * 32 + G * 4 + j) * 8 + q;
            const char* rowa = smem + BA_OFF + n * 128;
            int so = r + ((n & 1) << 2);
            uint4 v0 = *(const uint4*)(rowa + (so & 7) * 16);
            uint4 v1 = *(const uint4*)(rowa + ((so + 4) & 7) * 16);
            #pragma unroll
            for (int mt = 0; mt < 2; mt++) {
                MMA_F16(acc[mt][j], Aa[mt][0][0], Aa[mt][0][1], Aa[mt][0][2], Aa[mt][0][3], v0.x, v0.y);
                MMA_F16(acc[mt][j], Aa[mt][1][0], Aa[mt][1][1], Aa[mt][1][2], Aa[mt][1][3], v0.z, v0.w);
                MMA_F16(acc[mt][j], Aa[mt][2][0], Aa[mt][2][1], Aa[mt][2][2], Aa[mt][2][3], v1.x, v1.y);
                MMA_F16(acc[mt][j], Aa[mt][3][0], Aa[mt][3][1], Aa[mt][3][2], Aa[mt][3][3], v1.z, v1.w);
            }
        }
        #pragma unroll
        for (int j = 0; j < 4; j++) {
            int cb = (ng * 32 + G * 4 + j) * 8 + 2 * r;
            float h0 = shes[cb], h1 = shes[cb + 1];
            #pragma unroll
            for (int mt = 0; mt < 2; mt++) {
                mx[2 * mt]     = fmaxf(mx[2 * mt],
                                  fmaxf(acc[mt][j][0] - h0, acc[mt][j][1] - h1));
                mx[2 * mt + 1] = fmaxf(mx[2 * mt + 1],
                                  fmaxf(acc[mt][j][2] - h0, acc[mt][j][3] - h1));
            }
        }
    }
    #pragma unroll
    for (int i = 0; i < 4; i++) {
        mx[i] = fmaxf(mx[i], __shfl_xor_sync(0xffffffffu, mx[i], 1));
        mx[i] = fmaxf(mx[i], __shfl_xor_sync(0xffffffffu, mx[i], 2));
    }
    if (r == 0) {
        #pragma unroll
        for (int i = 0; i < 4; i++)
            atomicMax(&sapx[m0 + (i >> 1) * 16 + (i & 1) * 8 + q], ord_enc(mx[i]));
    }
    __syncthreads();

    // certified thresholds per covered row
    float maxEn = sqrtf(2.0f * __int_as_float(g_mhbits));
    float thr[4];
    #pragma unroll
    for (int i = 0; i < 4; i++) {
        int row = m0 + (i >> 1) * 16 + (i & 1) * 8 + q;
        unsigned u = sapx[row];
        float smax = __uint_as_float((u & 0x80000000u) ? (u & 0x7fffffffu) : ~u);
        thr[i] = smax - (2.2e-3f * sqrtf(snorm[row]) * maxEn + 1e-5f);
    }

    // ---- phase B: recompute identical MMAs, collect candidates ----
    #pragma unroll 1
    for (int G = 0; G < 8; G++) {
        float acc[2][4][4];
        #pragma unroll
        for (int mt = 0; mt < 2; mt++)
            #pragma unroll
            for (int j = 0; j < 4; j++)
                #pragma unroll
                for (int c = 0; c < 4; c++) acc[mt][j][c] = 0.f;
        #pragma unroll
        for (int j = 0; j < 4; j++) {
            int n = (ng * 32 + G * 4 + j) * 8 + q;
            const char* rowa = smem + BA_OFF + n * 128;
            int so = r + ((n & 1) << 2);
            uint4 v0 = *(const uint4*)(rowa + (so & 7) * 16);
            uint4 v1 = *(const uint4*)(rowa + ((so + 4) & 7) * 16);
            #pragma unroll
            for (int mt = 0; mt < 2; mt++) {
                MMA_F16(acc[mt][j], Aa[mt][0][0], Aa[mt][0][1], Aa[mt][0][2], Aa[mt][0][3], v0.x, v0.y);
                MMA_F16(acc[mt][j], Aa[mt][1][0], Aa[mt][1][1], Aa[mt][1][2], Aa[mt][1][3], v0.z, v0.w);
                MMA_F16(acc[mt][j], Aa[mt][2][0], Aa[mt][2][1], Aa[mt][2][2], Aa[mt][2][3], v1.x, v1.y);
                MMA_F16(acc[mt][j], Aa[mt][3][0], Aa[mt][3][1], Aa[mt][3][2], Aa[mt][3][3], v1.z, v1.w);
            }
        }
        #pragma unroll
        for (int j = 0; j < 4; j++) {
            int cb = (ng * 32 + G * 4 + j) * 8 + 2 * r;
            float h0 = shes[cb], h1 = shes[cb + 1];
            #pragma unroll
            for (int mt = 0; mt < 2; mt++) {
                float s[4] = {acc[mt][j][0] - h0, acc[mt][j][1] - h1,
                              acc[mt][j][2] - h0, acc[mt][j][3] - h1};
                #pragma unroll
                for (int e = 0; e < 4; e++) {
                    int half = e >> 1;
                    if (s[e] >= thr[2 * mt + half]) {
                        int row = m0 + mt * 16 + half * 8 + q;
                        int code = cb + (e & 1);
                        int pos = atomicAdd(scnt, 1);
                        if (pos < CAP) {
                            slist[pos] = ((unsigned)row << 16) | (unsigned)code;
                        } else {   // overflow fallback: rescore inline (rare)
                            float se = rescore(embed, sx, shes, row, code);
                            atomicMax(&sbest[row],
                                ((unsigned long long)ord_enc(se) << 32) |
                                (unsigned)(K - 1 - code));
                        }
                    }
                }
            }
        }
    }
    __syncthreads();

    // ---- phase C: exact rescore of collected candidates ----
    {
        int cnt = *scnt; if (cnt > CAP) cnt = CAP;
        for (int i = tid; i < cnt; i += T) {
            unsigned pc = slist[i];
            int row = pc >> 16, code = pc & 0xffff;
            float se = rescore(embed, sx, shes, row, code);
            atomicMax(&sbest[row],
                ((unsigned long long)ord_enc(se) << 32) | (unsigned)(K - 1 - code));
        }
    }
    __syncthreads();

    // outputs: gathered codebook rows (NHWC) + indices (float)
    #pragma unroll
    for (int t = 0; t < 8; t++) {
        int i = tid + t * T;                      // MT*16 = 2048 float4 writes
        int j = i >> 4, c4 = i & 15;
        int idx = (K - 1) - (int)(sbest[j] & 0xffffffffull);
        float4 v = *(const float4*)(embed + idx * D + (c4 << 2));
        *(float4*)(outq + ((size_t)(n0 + j)) * D + (c4 << 2)) = v;
    }
    if (outi && tid < MT)
        outi[n0 + tid] = (float)((K - 1) - (int)(sbest[tid] & 0xffffffffull));
}

// ---------------------------------------------------------------------------
extern "C" void kernel_launch(void* const* d_in, const int* in_sizes, int n_in,
                              void* d_out, int out_size) {
    const float* x = (const float*)d_in[0];
    const float* embed = (const float*)d_in[1];
    float* out = (float*)d_out;

    const int N = in_sizes[0] / D;
    float* outi = nullptr;
    if (out_size >= N * D + N) outi = out + (size_t)N * D;

    cudaFuncSetAttribute(vq_main, cudaFuncAttributeMaxDynamicSharedMemorySize, SMEM_SZ);
    vq_prep<<<K, D>>>(embed);
    vq_main<<<N / MT, T, SMEM_SZ>>>(x, embed, out, outi);
}